// round 7
// baseline (speedup 1.0000x reference)
#include <cuda_runtime.h>

#define T_STEPS 512
#define BATCH   64
#define DIN     256
#define DH      1024
#define DOUT    256
#define BH      (BATCH * DH)      // 65536
#define SCAN_CTAS 128
#define ARRIVALS  256             // 32 CTAs x 8 warps per chain domain

typedef unsigned long long ull;

// Scratch (device globals: allocation-free per harness rules)
__device__ float g_xp[T_STEPS * BH];       // [T][B][H] input projection
__device__ float g_hs[T_STEPS * BH];       // [T][B][H] hidden states
__device__ unsigned int g_bar8[T_STEPS * 8 * 32]; // (step, chain) counters, 128B apart

// ---- packed f32x2 helpers -------------------------------------------------
__device__ __forceinline__ ull pack2(float x) {
    ull r;
    asm("mov.b64 %0, {%1, %1};" : "=l"(r) : "f"(x));
    return r;
}
__device__ __forceinline__ ull pack2v(float lo, float hi) {
    ull r;
    asm("mov.b64 %0, {%1, %2};" : "=l"(r) : "f"(lo), "f"(hi));
    return r;
}
__device__ __forceinline__ void fma2(ull& acc, ull a, ull b) {
    asm("fma.rn.f32x2 %0, %1, %2, %0;" : "+l"(acc) : "l"(a), "l"(b));
}
__device__ __forceinline__ ull add2(ull a, ull b) {
    ull d;
    asm("add.rn.f32x2 %0, %1, %2;" : "=l"(d) : "l"(a), "l"(b));
    return d;
}
__device__ __forceinline__ void unpack2(ull v, float& lo, float& hi) {
    asm("mov.b64 {%0, %1}, %2;" : "=f"(lo), "=f"(hi) : "l"(v));
}

// ---------------------------------------------------------------------------
// Kernel A: x_proj[t][b][h] = sum_i inputs[b][t][i] * W_in[i][h] + bias[h]
// ---------------------------------------------------------------------------
__global__ void k_xproj(const float* __restrict__ x,
                        const float* __restrict__ Wi,
                        const float* __restrict__ bias) {
    const int t  = blockIdx.x;
    const int n0 = blockIdx.y * 64;
    __shared__ __align__(16) float As[64][36];
    __shared__ __align__(16) float Bs[32][68];
    const int tid = threadIdx.x;
    const int ty = tid >> 4, tx = tid & 15;
    ull acc[4][2] = {};

    for (int k0 = 0; k0 < DIN; k0 += 32) {
        for (int i = tid; i < 64 * 32; i += 256) {
            int m = i >> 5, kk = i & 31;
            As[m][kk] = x[(m * T_STEPS + t) * DIN + k0 + kk];
        }
        for (int i = tid; i < 32 * 64; i += 256) {
            int kk = i >> 6, n = i & 63;
            Bs[kk][n] = Wi[(k0 + kk) * DH + n0 + n];
        }
        __syncthreads();
#pragma unroll
        for (int kk = 0; kk < 32; kk++) {
            ulonglong2 bb = *(const ulonglong2*)&Bs[kk][tx * 4];
#pragma unroll
            for (int i = 0; i < 4; i++) {
                ull pa = pack2(As[ty * 4 + i][kk]);
                fma2(acc[i][0], pa, bb.x);
                fma2(acc[i][1], pa, bb.y);
            }
        }
        __syncthreads();
    }
    float4 bv = *(const float4*)&bias[n0 + tx * 4];
#pragma unroll
    for (int i = 0; i < 4; i++) {
        float4 v;
        unpack2(acc[i][0], v.x, v.y);
        unpack2(acc[i][1], v.z, v.w);
        v.x += bv.x; v.y += bv.y; v.z += bv.z; v.w += bv.w;
        *(float4*)&g_xp[t * BH + (ty * 4 + i) * DH + n0 + tx * 4] = v;
    }
}

// ---------------------------------------------------------------------------
// Kernel B: persistent scan, TWO interleaved 8-row chains per CTA.
// 128 CTAs (p = bid>>5 in [0,4), cb = bid&31). CTA handles chain p (rows
// 8p..8p+8) and chain p+4 (rows 8p+32..), cols cb*32..+32. Warp w owns 4
// cols; lane owns a 32-element K slice; W in 128 regs SHARED by both chains.
// Per-warp arrivals (no __syncthreads anywhere): each chain domain counts
// 256 warp arrivals. Chain A's barrier round-trip hides behind chain B's
// compute and vice versa.
// ---------------------------------------------------------------------------
__device__ __forceinline__ unsigned int* chain_ctr(int d, int t) {
    return &g_bar8[(t * 8 + d) * 32];
}

__device__ __forceinline__ void chain_arrive(int d, int t, int lane) {
    __syncwarp();
    if (lane == 0) {
        __threadfence();
        atomicAdd(chain_ctr(d, t), 1u);
    }
}

__device__ __forceinline__ void chain_wait(int d, int t, int lane, bool resetter) {
    if (lane == 0) {
        volatile unsigned int* ctr = (volatile unsigned int*)chain_ctr(d, t);
        while (*ctr < ARRIVALS) { }
        if (resetter && t > 0) *chain_ctr(d, t - 1) = 0;
    }
    __syncwarp();
    __threadfence();   // acquire: make others' h stores visible to this warp
}

// One recurrence step for an 8-row chain: acc over K, 5-level shfl tree,
// tanh, store. Lane mapping at the end: r = lane>>2, c = (lane>>1)&1,
// replica on lane bit0 (only bit0==0 stores).
__device__ __forceinline__ void chain_step(int t, int rowbase, int col0,
                                           int lane, const ull* W2 /*[8][4][2] flat*/) {
    const int r_o = lane >> 2;
    const int c_o = (lane >> 1) & 1;
    // prefetch xp (independent of h)
    float2 xv = *(const float2*)&g_xp[t * BH + (rowbase + r_o) * DH + col0 + c_o * 2];

    ull A[16] = {};   // item idx = r*2 + c
    const float* __restrict__ hp = g_hs + (t - 1) * BH;
#pragma unroll
    for (int r = 0; r < 8; r++) {
        const float* hrow = hp + (rowbase + r) * DH + lane * 4;
#pragma unroll
        for (int j = 0; j < 8; j++) {
            float4 hv = *(const float4*)(hrow + j * 128);
            ull h0 = pack2(hv.x), h1 = pack2(hv.y);
            ull h2 = pack2(hv.z), h3 = pack2(hv.w);
            const ull* Wj = W2 + j * 8;   // [kv][c2]
            fma2(A[r * 2 + 0], h0, Wj[0]); fma2(A[r * 2 + 1], h0, Wj[1]);
            fma2(A[r * 2 + 0], h1, Wj[2]); fma2(A[r * 2 + 1], h1, Wj[3]);
            fma2(A[r * 2 + 0], h2, Wj[4]); fma2(A[r * 2 + 1], h2, Wj[5]);
            fma2(A[r * 2 + 0], h3, Wj[6]); fma2(A[r * 2 + 1], h3, Wj[7]);
        }
    }

    // 5-level halving tree: 16 items -> 1 item (full 32-lane sum)
    bool up;
    up = (lane & 16) != 0;
#pragma unroll
    for (int i = 0; i < 8; i++) {
        ull send = up ? A[i] : A[i + 8];
        ull recv = __shfl_xor_sync(0xffffffffu, send, 16);
        ull keep = up ? A[i + 8] : A[i];
        A[i] = add2(keep, recv);
    }
    up = (lane & 8) != 0;
#pragma unroll
    for (int i = 0; i < 4; i++) {
        ull send = up ? A[i] : A[i + 4];
        ull recv = __shfl_xor_sync(0xffffffffu, send, 8);
        ull keep = up ? A[i + 4] : A[i];
        A[i] = add2(keep, recv);
    }
    up = (lane & 4) != 0;
#pragma unroll
    for (int i = 0; i < 2; i++) {
        ull send = up ? A[i] : A[i + 2];
        ull recv = __shfl_xor_sync(0xffffffffu, send, 4);
        ull keep = up ? A[i + 2] : A[i];
        A[i] = add2(keep, recv);
    }
    up = (lane & 2) != 0;
    {
        ull send = up ? A[0] : A[1];
        ull recv = __shfl_xor_sync(0xffffffffu, send, 2);
        ull keep = up ? A[1] : A[0];
        A[0] = add2(keep, recv);
    }
    {
        ull recv = __shfl_xor_sync(0xffffffffu, A[0], 1);
        A[0] = add2(A[0], recv);
    }

    float s0, s1;
    unpack2(A[0], s0, s1);
    if ((lane & 1) == 0) {
        float2 hv;
        hv.x = tanhf(xv.x + s0);
        hv.y = tanhf(xv.y + s1);
        *(float2*)&g_hs[t * BH + (rowbase + r_o) * DH + col0 + c_o * 2] = hv;
    }
}

__global__ void __launch_bounds__(256, 1) k_scan(const float* __restrict__ Wh) {
    const int tid  = threadIdx.x;
    const int w    = tid >> 5;
    const int lane = tid & 31;
    const int p    = blockIdx.x >> 5;          // 0..3
    const int cb   = blockIdx.x & 31;          // 0..31
    const int dA   = p,     rowA = p * 8;
    const int dB   = p + 4, rowB = p * 8 + 32;
    const int col0 = cb * 32 + w * 4;          // warp's 4 cols
    const bool resetter = (cb == 0) && (w == 0);

    // entry reset of last step's counters for this CTA's own domains
    if (resetter && lane == 0) {
        *chain_ctr(dA, T_STEPS - 1) = 0;
        *chain_ctr(dB, T_STEPS - 1) = 0;
    }

    // W columns in registers: W2[j][kv][c2], k = j*128 + lane*4 + kv
    ull W2[64];
#pragma unroll
    for (int j = 0; j < 8; j++)
#pragma unroll
        for (int kv = 0; kv < 4; kv++) {
            int k = j * 128 + lane * 4 + kv;
            ulonglong2 wv = *(const ulonglong2*)&Wh[k * DH + col0];
            W2[j * 8 + kv * 2 + 0] = wv.x;
            W2[j * 8 + kv * 2 + 1] = wv.y;
        }

    const int r_o = lane >> 2;
    const int c_o = (lane >> 1) & 1;

    // t = 0: h = tanh(xp) for both chains
    if ((lane & 1) == 0) {
        float2 xa = *(const float2*)&g_xp[(rowA + r_o) * DH + col0 + c_o * 2];
        float2 ha; ha.x = tanhf(xa.x); ha.y = tanhf(xa.y);
        *(float2*)&g_hs[(rowA + r_o) * DH + col0 + c_o * 2] = ha;
    }
    chain_arrive(dA, 0, lane);
    if ((lane & 1) == 0) {
        float2 xb = *(const float2*)&g_xp[(rowB + r_o) * DH + col0 + c_o * 2];
        float2 hb; hb.x = tanhf(xb.x); hb.y = tanhf(xb.y);
        *(float2*)&g_hs[(rowB + r_o) * DH + col0 + c_o * 2] = hb;
    }
    chain_arrive(dB, 0, lane);

    for (int t = 1; t < T_STEPS; t++) {
        chain_wait(dA, t - 1, lane, resetter);
        chain_step(t, rowA, col0, lane, W2);
        chain_arrive(dA, t, lane);

        chain_wait(dB, t - 1, lane, resetter);
        chain_step(t, rowB, col0, lane, W2);
        chain_arrive(dB, t, lane);
    }
}

// ---------------------------------------------------------------------------
// Kernel C: out[b][t][o] = sum_h hs[t][b][h] * W_out[h][o] + bias[o]
// ---------------------------------------------------------------------------
__global__ void k_out(const float* __restrict__ Wo,
                      const float* __restrict__ bias,
                      float* __restrict__ out) {
    const int t  = blockIdx.x;
    const int n0 = blockIdx.y * 64;
    __shared__ __align__(16) float As[64][36];
    __shared__ __align__(16) float Bs[32][68];
    const int tid = threadIdx.x;
    const int ty = tid >> 4, tx = tid & 15;
    ull acc[4][2] = {};

    for (int k0 = 0; k0 < DH; k0 += 32) {
        for (int i = tid; i < 64 * 32; i += 256) {
            int m = i >> 5, kk = i & 31;
            As[m][kk] = g_hs[t * BH + m * DH + k0 + kk];
        }
        for (int i = tid; i < 32 * 64; i += 256) {
            int kk = i >> 6, n = i & 63;
            Bs[kk][n] = Wo[(k0 + kk) * DOUT + n0 + n];
        }
        __syncthreads();
#pragma unroll
        for (int kk = 0; kk < 32; kk++) {
            ulonglong2 bb = *(const ulonglong2*)&Bs[kk][tx * 4];
#pragma unroll
            for (int i = 0; i < 4; i++) {
                ull pa = pack2(As[ty * 4 + i][kk]);
                fma2(acc[i][0], pa, bb.x);
                fma2(acc[i][1], pa, bb.y);
            }
        }
        __syncthreads();
    }
    float4 bv = *(const float4*)&bias[n0 + tx * 4];
#pragma unroll
    for (int i = 0; i < 4; i++) {
        float4 v;
        unpack2(acc[i][0], v.x, v.y);
        unpack2(acc[i][1], v.z, v.w);
        v.x += bv.x; v.y += bv.y; v.z += bv.z; v.w += bv.w;
        *(float4*)&out[((ty * 4 + i) * T_STEPS + t) * DOUT + n0 + tx * 4] = v;
    }
}

// ---------------------------------------------------------------------------
extern "C" void kernel_launch(void* const* d_in, const int* in_sizes, int n_in,
                              void* d_out, int out_size) {
    const float* x  = (const float*)d_in[0];  // inputs [B,T,DIN]
    const float* Wi = (const float*)d_in[1];  // input_kernel [DIN,DH]
    const float* Wh = (const float*)d_in[2];  // hidden_kernel [DH,DH]
    const float* bh = (const float*)d_in[3];  // hidden_bias [DH]
    const float* Wo = (const float*)d_in[4];  // output_kernel [DH,DOUT]
    const float* bo = (const float*)d_in[5];  // output_bias [DOUT]
    float* out = (float*)d_out;               // [B,T,DOUT]

    k_xproj<<<dim3(T_STEPS, DH / 64), 256>>>(x, Wi, bh);
    k_scan<<<SCAN_CTAS, 256>>>(Wh);
    k_out<<<dim3(T_STEPS, DOUT / 64), 256>>>(Wo, bo, out);
}

// round 8
// speedup vs baseline: 1.1338x; 1.1338x over previous
#include <cuda_runtime.h>

#define T_STEPS 512
#define BATCH   64
#define DIN     256
#define DH      1024
#define DOUT    256
#define BH      (BATCH * DH)      // 65536
#define SCAN_CTAS 128
#define ARRIVALS  256             // 32 CTAs x 8 warps per row-group domain

typedef unsigned long long ull;

// Scratch (device globals: allocation-free per harness rules)
__device__ float g_xp[T_STEPS * BH];       // [T][B][H] input projection
__device__ float g_hs[T_STEPS * BH];       // [T][B][H] hidden states
__device__ unsigned int g_barG[T_STEPS * 4 * 32]; // (step, rowgroup) counters, 128B apart

// ---- packed f32x2 helpers -------------------------------------------------
__device__ __forceinline__ ull pack2(float x) {
    ull r;
    asm("mov.b64 %0, {%1, %1};" : "=l"(r) : "f"(x));
    return r;
}
__device__ __forceinline__ void fma2(ull& acc, ull a, ull b) {
    asm("fma.rn.f32x2 %0, %1, %2, %0;" : "+l"(acc) : "l"(a), "l"(b));
}
__device__ __forceinline__ ull add2(ull a, ull b) {
    ull d;
    asm("add.rn.f32x2 %0, %1, %2;" : "=l"(d) : "l"(a), "l"(b));
    return d;
}
__device__ __forceinline__ void unpack2(ull v, float& lo, float& hi) {
    asm("mov.b64 {%0, %1}, %2;" : "=f"(lo), "=f"(hi) : "l"(v));
}

// ---------------------------------------------------------------------------
// Kernel A: x_proj[t][b][h] = sum_i inputs[b][t][i] * W_in[i][h] + bias[h]
// ---------------------------------------------------------------------------
__global__ void k_xproj(const float* __restrict__ x,
                        const float* __restrict__ Wi,
                        const float* __restrict__ bias) {
    const int t  = blockIdx.x;
    const int n0 = blockIdx.y * 64;
    __shared__ __align__(16) float As[64][36];
    __shared__ __align__(16) float Bs[32][68];
    const int tid = threadIdx.x;
    const int ty = tid >> 4, tx = tid & 15;
    ull acc[4][2] = {};

    for (int k0 = 0; k0 < DIN; k0 += 32) {
        for (int i = tid; i < 64 * 32; i += 256) {
            int m = i >> 5, kk = i & 31;
            As[m][kk] = x[(m * T_STEPS + t) * DIN + k0 + kk];
        }
        for (int i = tid; i < 32 * 64; i += 256) {
            int kk = i >> 6, n = i & 63;
            Bs[kk][n] = Wi[(k0 + kk) * DH + n0 + n];
        }
        __syncthreads();
#pragma unroll
        for (int kk = 0; kk < 32; kk++) {
            ulonglong2 bb = *(const ulonglong2*)&Bs[kk][tx * 4];
#pragma unroll
            for (int i = 0; i < 4; i++) {
                ull pa = pack2(As[ty * 4 + i][kk]);
                fma2(acc[i][0], pa, bb.x);
                fma2(acc[i][1], pa, bb.y);
            }
        }
        __syncthreads();
    }
    float4 bv = *(const float4*)&bias[n0 + tx * 4];
#pragma unroll
    for (int i = 0; i < 4; i++) {
        float4 v;
        unpack2(acc[i][0], v.x, v.y);
        unpack2(acc[i][1], v.z, v.w);
        v.x += bv.x; v.y += bv.y; v.z += bv.z; v.w += bv.w;
        *(float4*)&g_xp[t * BH + (ty * 4 + i) * DH + n0 + tx * 4] = v;
    }
}

// ---------------------------------------------------------------------------
// Kernel B: persistent scan, R4 compute + warp-decoupled row-group barriers.
// 128 CTAs (rb = bid>>5 row group of 16 rows, cb = bid&31 col block of 32).
// Warp w owns 4 cols; lane owns a scrambled 32-float K slice; W in 128 regs.
// Barrier: per-(step,rowgroup) counter. Arrivals = red.release.gpu per WARP
// (REDG: ~0.85cyc/op serialized, 256 arrivals ~ 220cyc). Wait = lane0
// ld.acquire.gpu poll + __syncwarp. No __syncthreads anywhere in the scan.
// ---------------------------------------------------------------------------
__device__ __forceinline__ unsigned int* rg_ctr(int rb, int t) {
    return &g_barG[(t * 4 + rb) * 32];
}

__device__ __forceinline__ void rg_arrive(int rb, int t, int lane) {
    __syncwarp();   // all lanes' h stores happen-before lane0's release
    if (lane == 0) {
        asm volatile("red.release.gpu.global.add.u32 [%0], 1;"
                     :: "l"(rg_ctr(rb, t)) : "memory");
    }
}

__device__ __forceinline__ void rg_wait(int rb, int t, int lane, bool resetter) {
    if (lane == 0) {
        unsigned int v;
        while (true) {
            asm volatile("ld.acquire.gpu.global.u32 %0, [%1];"
                         : "=r"(v) : "l"(rg_ctr(rb, t)) : "memory");
            if (v >= ARRIVALS) break;
            __nanosleep(32);
        }
        // everyone arrived at t => everyone passed wait(t-1): safe to reset t-1
        if (resetter && t >= 1) {
            asm volatile("st.global.relaxed.gpu.u32 [%0], 0;"
                         :: "l"(rg_ctr(rb, t - 1)) : "memory");
        }
    }
    __syncwarp();   // acquire edge propagates to all lanes
}

__global__ void __launch_bounds__(256, 1) k_scan(const float* __restrict__ Wh) {
    const int tid  = threadIdx.x;
    const int w    = tid >> 5;
    const int lane = tid & 31;
    const int rb   = blockIdx.x >> 5;          // 0..3 row group
    const int cb   = blockIdx.x & 31;          // 0..31 col block
    const int row0 = rb * 16;
    const int col0 = cb * 32 + w * 4;          // warp's 4 cols
    const int klane = (lane + blockIdx.x) & 31;
    const bool resetter = (cb == 0) && (w == 0);

    // entry reset of counters left set by previous launch (t = 510, 511)
    if (resetter && lane == 0) {
        *rg_ctr(rb, T_STEPS - 1) = 0;
        *rg_ctr(rb, T_STEPS - 2) = 0;
    }

    // W registers: W2[j][kv][c2] = packed cols (col0+2c2, col0+2c2+1)
    // at k = j*128 + klane*4 + kv.  64 x b64 = 128 regs, static-indexed.
    ull W2[8][4][2];
#pragma unroll
    for (int j = 0; j < 8; j++)
#pragma unroll
        for (int kv = 0; kv < 4; kv++) {
            int k = j * 128 + klane * 4 + kv;
            ulonglong2 wv = *(const ulonglong2*)&Wh[k * DH + col0];
            W2[j][kv][0] = wv.x;
            W2[j][kv][1] = wv.y;
        }

    // Output mapping after reduction: lane -> (row = lane>>1, colpair = lane&1)
    const int orow = row0 + (lane >> 1);
    const int ocol = col0 + (lane & 1) * 2;

    // t = 0: h = tanh(xp)
    {
        float2 xv = *(const float2*)&g_xp[orow * DH + ocol];
        float2 hv;
        hv.x = tanhf(xv.x);
        hv.y = tanhf(xv.y);
        *(float2*)&g_hs[orow * DH + ocol] = hv;
    }
    rg_arrive(rb, 0, lane);

    for (int t = 1; t < T_STEPS; t++) {
        // prefetch xp for this step BEFORE waiting (independent of h)
        float2 xv = *(const float2*)&g_xp[t * BH + orow * DH + ocol];

        rg_wait(rb, t - 1, lane, resetter);

        ull acc[16][2] = {};
        const float* __restrict__ hp = g_hs + (t - 1) * BH;

#pragma unroll
        for (int mi = 0; mi < 16; mi++) {
            const float* hrow = hp + (row0 + mi) * DH + klane * 4;
#pragma unroll
            for (int j = 0; j < 8; j++) {
                float4 hv = *(const float4*)(hrow + j * 128);
                ull h0 = pack2(hv.x), h1 = pack2(hv.y);
                ull h2 = pack2(hv.z), h3 = pack2(hv.w);
                fma2(acc[mi][0], h0, W2[j][0][0]); fma2(acc[mi][1], h0, W2[j][0][1]);
                fma2(acc[mi][0], h1, W2[j][1][0]); fma2(acc[mi][1], h1, W2[j][1][1]);
                fma2(acc[mi][0], h2, W2[j][2][0]); fma2(acc[mi][1], h2, W2[j][2][1]);
                fma2(acc[mi][0], h3, W2[j][3][0]); fma2(acc[mi][1], h3, W2[j][3][1]);
            }
        }

        // cross-lane reduce (each output summed over 32 lanes' k-slices)
        bool up;
        up = (lane & 16) != 0;
#pragma unroll
        for (int i = 0; i < 8; i++)
#pragma unroll
            for (int c = 0; c < 2; c++) {
                ull send = up ? acc[i][c] : acc[i + 8][c];
                ull recv = __shfl_xor_sync(0xffffffffu, send, 16);
                ull keep = up ? acc[i + 8][c] : acc[i][c];
                acc[i][c] = add2(keep, recv);
            }
        up = (lane & 8) != 0;
#pragma unroll
        for (int i = 0; i < 4; i++)
#pragma unroll
            for (int c = 0; c < 2; c++) {
                ull send = up ? acc[i][c] : acc[i + 4][c];
                ull recv = __shfl_xor_sync(0xffffffffu, send, 8);
                ull keep = up ? acc[i + 4][c] : acc[i][c];
                acc[i][c] = add2(keep, recv);
            }
        up = (lane & 4) != 0;
#pragma unroll
        for (int i = 0; i < 2; i++)
#pragma unroll
            for (int c = 0; c < 2; c++) {
                ull send = up ? acc[i][c] : acc[i + 2][c];
                ull recv = __shfl_xor_sync(0xffffffffu, send, 4);
                ull keep = up ? acc[i + 2][c] : acc[i][c];
                acc[i][c] = add2(keep, recv);
            }
        up = (lane & 2) != 0;
#pragma unroll
        for (int c = 0; c < 2; c++) {
            ull send = up ? acc[0][c] : acc[1][c];
            ull recv = __shfl_xor_sync(0xffffffffu, send, 2);
            ull keep = up ? acc[1][c] : acc[0][c];
            acc[0][c] = add2(keep, recv);
        }
        up = (lane & 1) != 0;
        {
            ull send = up ? acc[0][0] : acc[0][1];
            ull recv = __shfl_xor_sync(0xffffffffu, send, 1);
            ull keep = up ? acc[0][1] : acc[0][0];
            acc[0][0] = add2(keep, recv);
        }

        float s0, s1;
        unpack2(acc[0][0], s0, s1);
        float2 hv;
        hv.x = tanhf(xv.x + s0);
        hv.y = tanhf(xv.y + s1);
        *(float2*)&g_hs[t * BH + orow * DH + ocol] = hv;

        rg_arrive(rb, t, lane);
    }
}

// ---------------------------------------------------------------------------
// Kernel C: out[b][t][o] = sum_h hs[t][b][h] * W_out[h][o] + bias[o]
// ---------------------------------------------------------------------------
__global__ void k_out(const float* __restrict__ Wo,
                      const float* __restrict__ bias,
                      float* __restrict__ out) {
    const int t  = blockIdx.x;
    const int n0 = blockIdx.y * 64;
    __shared__ __align__(16) float As[64][36];
    __shared__ __align__(16) float Bs[32][68];
    const int tid = threadIdx.x;
    const int ty = tid >> 4, tx = tid & 15;
    ull acc[4][2] = {};

    for (int k0 = 0; k0 < DH; k0 += 32) {
        for (int i = tid; i < 64 * 32; i += 256) {
            int m = i >> 5, kk = i & 31;
            As[m][kk] = g_hs[t * BH + m * DH + k0 + kk];
        }
        for (int i = tid; i < 32 * 64; i += 256) {
            int kk = i >> 6, n = i & 63;
            Bs[kk][n] = Wo[(k0 + kk) * DOUT + n0 + n];
        }
        __syncthreads();
#pragma unroll
        for (int kk = 0; kk < 32; kk++) {
            ulonglong2 bb = *(const ulonglong2*)&Bs[kk][tx * 4];
#pragma unroll
            for (int i = 0; i < 4; i++) {
                ull pa = pack2(As[ty * 4 + i][kk]);
                fma2(acc[i][0], pa, bb.x);
                fma2(acc[i][1], pa, bb.y);
            }
        }
        __syncthreads();
    }
    float4 bv = *(const float4*)&bias[n0 + tx * 4];
#pragma unroll
    for (int i = 0; i < 4; i++) {
        float4 v;
        unpack2(acc[i][0], v.x, v.y);
        unpack2(acc[i][1], v.z, v.w);
        v.x += bv.x; v.y += bv.y; v.z += bv.z; v.w += bv.w;
        *(float4*)&out[((ty * 4 + i) * T_STEPS + t) * DOUT + n0 + tx * 4] = v;
    }
}

// ---------------------------------------------------------------------------
extern "C" void kernel_launch(void* const* d_in, const int* in_sizes, int n_in,
                              void* d_out, int out_size) {
    const float* x  = (const float*)d_in[0];  // inputs [B,T,DIN]
    const float* Wi = (const float*)d_in[1];  // input_kernel [DIN,DH]
    const float* Wh = (const float*)d_in[2];  // hidden_kernel [DH,DH]
    const float* bh = (const float*)d_in[3];  // hidden_bias [DH]
    const float* Wo = (const float*)d_in[4];  // output_kernel [DH,DOUT]
    const float* bo = (const float*)d_in[5];  // output_bias [DOUT]
    float* out = (float*)d_out;               // [B,T,DOUT]

    k_xproj<<<dim3(T_STEPS, DH / 64), 256>>>(x, Wi, bh);
    k_scan<<<SCAN_CTAS, 256>>>(Wh);
    k_out<<<dim3(T_STEPS, DOUT / 64), 256>>>(Wo, bo, out);
}

// round 9
// speedup vs baseline: 2.8449x; 2.5092x over previous
#include <cuda_runtime.h>

#define T_STEPS 512
#define BATCH   64
#define DIN     256
#define DH      1024
#define DOUT    256
#define BH      (BATCH * DH)      // 65536
#define SCAN_CTAS 128
#define DOM_ARRIVALS 32           // 32 CTAs per row-group domain

typedef unsigned long long ull;

// Scratch (device globals: allocation-free per harness rules)
__device__ float g_xp[T_STEPS * BH];       // [T][B][H] input projection
__device__ float g_hs[T_STEPS * BH];       // [T][B][H] hidden states
__device__ unsigned int g_barG[T_STEPS * 4 * 32]; // (step, rowgroup) counters, 128B apart

// ---- packed f32x2 helpers -------------------------------------------------
__device__ __forceinline__ ull pack2(float x) {
    ull r;
    asm("mov.b64 %0, {%1, %1};" : "=l"(r) : "f"(x));
    return r;
}
__device__ __forceinline__ void fma2(ull& acc, ull a, ull b) {
    asm("fma.rn.f32x2 %0, %1, %2, %0;" : "+l"(acc) : "l"(a), "l"(b));
}
__device__ __forceinline__ ull add2(ull a, ull b) {
    ull d;
    asm("add.rn.f32x2 %0, %1, %2;" : "=l"(d) : "l"(a), "l"(b));
    return d;
}
__device__ __forceinline__ void unpack2(ull v, float& lo, float& hi) {
    asm("mov.b64 {%0, %1}, %2;" : "=f"(lo), "=f"(hi) : "l"(v));
}

// ---------------------------------------------------------------------------
// Kernel A: x_proj[t][b][h] = sum_i inputs[b][t][i] * W_in[i][h] + bias[h]
// ---------------------------------------------------------------------------
__global__ void k_xproj(const float* __restrict__ x,
                        const float* __restrict__ Wi,
                        const float* __restrict__ bias) {
    const int t  = blockIdx.x;
    const int n0 = blockIdx.y * 64;
    __shared__ __align__(16) float As[64][36];
    __shared__ __align__(16) float Bs[32][68];
    const int tid = threadIdx.x;
    const int ty = tid >> 4, tx = tid & 15;
    ull acc[4][2] = {};

    for (int k0 = 0; k0 < DIN; k0 += 32) {
        for (int i = tid; i < 64 * 32; i += 256) {
            int m = i >> 5, kk = i & 31;
            As[m][kk] = x[(m * T_STEPS + t) * DIN + k0 + kk];
        }
        for (int i = tid; i < 32 * 64; i += 256) {
            int kk = i >> 6, n = i & 63;
            Bs[kk][n] = Wi[(k0 + kk) * DH + n0 + n];
        }
        __syncthreads();
#pragma unroll
        for (int kk = 0; kk < 32; kk++) {
            ulonglong2 bb = *(const ulonglong2*)&Bs[kk][tx * 4];
#pragma unroll
            for (int i = 0; i < 4; i++) {
                ull pa = pack2(As[ty * 4 + i][kk]);
                fma2(acc[i][0], pa, bb.x);
                fma2(acc[i][1], pa, bb.y);
            }
        }
        __syncthreads();
    }
    float4 bv = *(const float4*)&bias[n0 + tx * 4];
#pragma unroll
    for (int i = 0; i < 4; i++) {
        float4 v;
        unpack2(acc[i][0], v.x, v.y);
        unpack2(acc[i][1], v.z, v.w);
        v.x += bv.x; v.y += bv.y; v.z += bv.z; v.w += bv.w;
        *(float4*)&g_xp[t * BH + (ty * 4 + i) * DH + n0 + tx * 4] = v;
    }
}

// ---------------------------------------------------------------------------
// Kernel B: persistent scan. R4 compute (W in 128 regs, direct LDG of h,
// shfl tree) + 4 independent 32-CTA row-group barrier domains with
// red.release arrivals and relaxed-spin + single-acquire waits.
// Topology per barrier: ONE arriver + ONE poller per CTA (thread 0),
// __syncthreads-coupled CTA (the only topology that has worked).
// ---------------------------------------------------------------------------
__device__ __forceinline__ unsigned int* rg_ctr(int rb, int t) {
    return &g_barG[(t * 4 + rb) * 32];
}

__device__ __forceinline__ void rg_barrier(int t, int rb, bool resetter) {
    __syncthreads();   // all h stores of this CTA happen-before thread0 release
    if (threadIdx.x == 0) {
        unsigned int* ctr = rg_ctr(rb, t);
        // release arrival, no return value (REDG, not ATOMG)
        asm volatile("red.release.gpu.global.add.u32 [%0], 1;"
                     :: "l"(ctr) : "memory");
        // relaxed spin; one acquire confirm after detection
        unsigned int v;
        do {
            asm volatile("ld.relaxed.gpu.global.u32 %0, [%1];"
                         : "=r"(v) : "l"(ctr) : "memory");
        } while (v < DOM_ARRIVALS);
        asm volatile("ld.acquire.gpu.global.u32 %0, [%1];"
                     : "=r"(v) : "l"(ctr) : "memory");
        // all CTAs arrived at t => all passed wait(t-1): t-1 counter is dead
        if (resetter && t > 0) {
            asm volatile("st.relaxed.gpu.global.u32 [%0], 0;"
                         :: "l"(rg_ctr(rb, t - 1)) : "memory");
        }
    }
    __syncthreads();   // acquire edge propagates to all threads
}

__global__ void __launch_bounds__(256, 1) k_scan(const float* __restrict__ Wh) {
    const int tid  = threadIdx.x;
    const int w    = tid >> 5;
    const int lane = tid & 31;
    const int rb   = blockIdx.x >> 5;          // 0..3 row group
    const int cb   = blockIdx.x & 31;          // 0..31 col block
    const int row0 = rb * 16;
    const int col0 = cb * 32 + w * 4;          // warp's 4 cols
    const int klane = (lane + blockIdx.x) & 31;
    const bool resetter = (cb == 0);

    // entry reset: only counter t = T_STEPS-2 survives the previous launch
    // (last barrier used is t=510; its reset never happens in-loop)
    if (resetter && tid == 0) {
        *rg_ctr(rb, T_STEPS - 2) = 0;
    }

    // W registers: W2[j][kv][c2] = packed cols (col0+2c2, col0+2c2+1)
    // at k = j*128 + klane*4 + kv.  64 x b64 = 128 regs, static-indexed.
    ull W2[8][4][2];
#pragma unroll
    for (int j = 0; j < 8; j++)
#pragma unroll
        for (int kv = 0; kv < 4; kv++) {
            int k = j * 128 + klane * 4 + kv;
            ulonglong2 wv = *(const ulonglong2*)&Wh[k * DH + col0];
            W2[j][kv][0] = wv.x;
            W2[j][kv][1] = wv.y;
        }

    // Output mapping after reduction: lane -> (row = lane>>1, colpair = lane&1)
    const int orow = row0 + (lane >> 1);
    const int ocol = col0 + (lane & 1) * 2;

    // t = 0: h = tanh(xp)
    {
        float2 xv = *(const float2*)&g_xp[orow * DH + ocol];
        float2 hv;
        hv.x = tanhf(xv.x);
        hv.y = tanhf(xv.y);
        *(float2*)&g_hs[orow * DH + ocol] = hv;
    }
    rg_barrier(0, rb, resetter);

    for (int t = 1; t < T_STEPS; t++) {
        // prefetch xp for this step (independent of h, hides DRAM latency)
        float2 xv = *(const float2*)&g_xp[t * BH + orow * DH + ocol];

        ull acc[16][2] = {};
        const float* __restrict__ hp = g_hs + (t - 1) * BH;

#pragma unroll
        for (int mi = 0; mi < 16; mi++) {
            const float* hrow = hp + (row0 + mi) * DH + klane * 4;
#pragma unroll
            for (int j = 0; j < 8; j++) {
                float4 hv = *(const float4*)(hrow + j * 128);
                ull h0 = pack2(hv.x), h1 = pack2(hv.y);
                ull h2 = pack2(hv.z), h3 = pack2(hv.w);
                fma2(acc[mi][0], h0, W2[j][0][0]); fma2(acc[mi][1], h0, W2[j][0][1]);
                fma2(acc[mi][0], h1, W2[j][1][0]); fma2(acc[mi][1], h1, W2[j][1][1]);
                fma2(acc[mi][0], h2, W2[j][2][0]); fma2(acc[mi][1], h2, W2[j][2][1]);
                fma2(acc[mi][0], h3, W2[j][3][0]); fma2(acc[mi][1], h3, W2[j][3][1]);
            }
        }

        // cross-lane reduce (each output summed over 32 lanes' k-slices)
        bool up;
        up = (lane & 16) != 0;
#pragma unroll
        for (int i = 0; i < 8; i++)
#pragma unroll
            for (int c = 0; c < 2; c++) {
                ull send = up ? acc[i][c] : acc[i + 8][c];
                ull recv = __shfl_xor_sync(0xffffffffu, send, 16);
                ull keep = up ? acc[i + 8][c] : acc[i][c];
                acc[i][c] = add2(keep, recv);
            }
        up = (lane & 8) != 0;
#pragma unroll
        for (int i = 0; i < 4; i++)
#pragma unroll
            for (int c = 0; c < 2; c++) {
                ull send = up ? acc[i][c] : acc[i + 4][c];
                ull recv = __shfl_xor_sync(0xffffffffu, send, 8);
                ull keep = up ? acc[i + 4][c] : acc[i][c];
                acc[i][c] = add2(keep, recv);
            }
        up = (lane & 4) != 0;
#pragma unroll
        for (int i = 0; i < 2; i++)
#pragma unroll
            for (int c = 0; c < 2; c++) {
                ull send = up ? acc[i][c] : acc[i + 2][c];
                ull recv = __shfl_xor_sync(0xffffffffu, send, 4);
                ull keep = up ? acc[i + 2][c] : acc[i][c];
                acc[i][c] = add2(keep, recv);
            }
        up = (lane & 2) != 0;
#pragma unroll
        for (int c = 0; c < 2; c++) {
            ull send = up ? acc[0][c] : acc[1][c];
            ull recv = __shfl_xor_sync(0xffffffffu, send, 2);
            ull keep = up ? acc[1][c] : acc[0][c];
            acc[0][c] = add2(keep, recv);
        }
        up = (lane & 1) != 0;
        {
            ull send = up ? acc[0][0] : acc[0][1];
            ull recv = __shfl_xor_sync(0xffffffffu, send, 1);
            ull keep = up ? acc[0][1] : acc[0][0];
            acc[0][0] = add2(keep, recv);
        }

        float s0, s1;
        unpack2(acc[0][0], s0, s1);
        float2 hv;
        hv.x = tanhf(xv.x + s0);
        hv.y = tanhf(xv.y + s1);
        *(float2*)&g_hs[t * BH + orow * DH + ocol] = hv;

        if (t != T_STEPS - 1)          // no barrier after the final store
            rg_barrier(t, rb, resetter);
    }
}

// ---------------------------------------------------------------------------
// Kernel C: out[b][t][o] = sum_h hs[t][b][h] * W_out[h][o] + bias[o]
// ---------------------------------------------------------------------------
__global__ void k_out(const float* __restrict__ Wo,
                      const float* __restrict__ bias,
                      float* __restrict__ out) {
    const int t  = blockIdx.x;
    const int n0 = blockIdx.y * 64;
    __shared__ __align__(16) float As[64][36];
    __shared__ __align__(16) float Bs[32][68];
    const int tid = threadIdx.x;
    const int ty = tid >> 4, tx = tid & 15;
    ull acc[4][2] = {};

    for (int k0 = 0; k0 < DH; k0 += 32) {
        for (int i = tid; i < 64 * 32; i += 256) {
            int m = i >> 5, kk = i & 31;
            As[m][kk] = g_hs[t * BH + m * DH + k0 + kk];
        }
        for (int i = tid; i < 32 * 64; i += 256) {
            int kk = i >> 6, n = i & 63;
            Bs[kk][n] = Wo[(k0 + kk) * DOUT + n0 + n];
        }
        __syncthreads();
#pragma unroll
        for (int kk = 0; kk < 32; kk++) {
            ulonglong2 bb = *(const ulonglong2*)&Bs[kk][tx * 4];
#pragma unroll
            for (int i = 0; i < 4; i++) {
                ull pa = pack2(As[ty * 4 + i][kk]);
                fma2(acc[i][0], pa, bb.x);
                fma2(acc[i][1], pa, bb.y);
            }
        }
        __syncthreads();
    }
    float4 bv = *(const float4*)&bias[n0 + tx * 4];
#pragma unroll
    for (int i = 0; i < 4; i++) {
        float4 v;
        unpack2(acc[i][0], v.x, v.y);
        unpack2(acc[i][1], v.z, v.w);
        v.x += bv.x; v.y += bv.y; v.z += bv.z; v.w += bv.w;
        *(float4*)&out[((ty * 4 + i) * T_STEPS + t) * DOUT + n0 + tx * 4] = v;
    }
}

// ---------------------------------------------------------------------------
extern "C" void kernel_launch(void* const* d_in, const int* in_sizes, int n_in,
                              void* d_out, int out_size) {
    const float* x  = (const float*)d_in[0];  // inputs [B,T,DIN]
    const float* Wi = (const float*)d_in[1];  // input_kernel [DIN,DH]
    const float* Wh = (const float*)d_in[2];  // hidden_kernel [DH,DH]
    const float* bh = (const float*)d_in[3];  // hidden_bias [DH]
    const float* Wo = (const float*)d_in[4];  // output_kernel [DH,DOUT]
    const float* bo = (const float*)d_in[5];  // output_bias [DOUT]
    float* out = (float*)d_out;               // [B,T,DOUT]

    k_xproj<<<dim3(T_STEPS, DH / 64), 256>>>(x, Wi, bh);
    k_scan<<<SCAN_CTAS, 256>>>(Wh);
    k_out<<<dim3(T_STEPS, DOUT / 64), 256>>>(Wo, bo, out);
}

// round 10
// speedup vs baseline: 4.0976x; 1.4403x over previous
#include <cuda_runtime.h>
#include <cuda_bf16.h>

#define T_STEPS 512
#define BATCH   64
#define DIN     256
#define DH      1024
#define DOUT    256
#define BH      (BATCH * DH)      // 65536
#define SCAN_CTAS 128
#define DOM_ARRIVALS 32           // 32 CTAs per row-group domain
#define SA_STRIDE 1032            // padded bf16 row stride (2064B: conflict-free LDSM)

typedef unsigned long long ull;
typedef unsigned int uint32;

// Scratch (device globals: allocation-free per harness rules)
__device__ float g_xp[T_STEPS * BH];                 // [T][B][H] input projection
__device__ __nv_bfloat16 g_hs_hi[T_STEPS * BH];      // h high bf16
__device__ __nv_bfloat16 g_hs_lo[T_STEPS * BH];      // h residual bf16
__device__ unsigned int g_barG[T_STEPS * 4 * 32];    // (step, rowgroup) counters, 128B apart

// ---- packed f32x2 helpers (for the two dense GEMM kernels) ----------------
__device__ __forceinline__ ull pack2(float x) {
    ull r;
    asm("mov.b64 %0, {%1, %1};" : "=l"(r) : "f"(x));
    return r;
}
__device__ __forceinline__ void fma2(ull& acc, ull a, ull b) {
    asm("fma.rn.f32x2 %0, %1, %2, %0;" : "+l"(acc) : "l"(a), "l"(b));
}
__device__ __forceinline__ void unpack2(ull v, float& lo, float& hi) {
    asm("mov.b64 {%0, %1}, %2;" : "=f"(lo), "=f"(hi) : "l"(v));
}

// ---- bf16 split helpers ---------------------------------------------------
__device__ __forceinline__ void split_bf16(float v, __nv_bfloat16& hi, __nv_bfloat16& lo) {
    hi = __float2bfloat16_rn(v);
    lo = __float2bfloat16_rn(v - __bfloat162float(hi));
}
// pack two k-consecutive bf16 (k in low half) into a .b32 mma operand
__device__ __forceinline__ uint32 pack_bf2(__nv_bfloat16 a, __nv_bfloat16 b) {
    __nv_bfloat162 p;
    p.x = a; p.y = b;
    return *(uint32*)&p;
}

// ---------------------------------------------------------------------------
// Kernel A: x_proj[t][b][h] = sum_i inputs[b][t][i] * W_in[i][h] + bias[h]
// ---------------------------------------------------------------------------
__global__ void k_xproj(const float* __restrict__ x,
                        const float* __restrict__ Wi,
                        const float* __restrict__ bias) {
    const int t  = blockIdx.x;
    const int n0 = blockIdx.y * 64;
    __shared__ __align__(16) float As[64][36];
    __shared__ __align__(16) float Bs[32][68];
    const int tid = threadIdx.x;
    const int ty = tid >> 4, tx = tid & 15;
    ull acc[4][2] = {};

    for (int k0 = 0; k0 < DIN; k0 += 32) {
        for (int i = tid; i < 64 * 32; i += 256) {
            int m = i >> 5, kk = i & 31;
            As[m][kk] = x[(m * T_STEPS + t) * DIN + k0 + kk];
        }
        for (int i = tid; i < 32 * 64; i += 256) {
            int kk = i >> 6, n = i & 63;
            Bs[kk][n] = Wi[(k0 + kk) * DH + n0 + n];
        }
        __syncthreads();
#pragma unroll
        for (int kk = 0; kk < 32; kk++) {
            ulonglong2 bb = *(const ulonglong2*)&Bs[kk][tx * 4];
#pragma unroll
            for (int i = 0; i < 4; i++) {
                ull pa = pack2(As[ty * 4 + i][kk]);
                fma2(acc[i][0], pa, bb.x);
                fma2(acc[i][1], pa, bb.y);
            }
        }
        __syncthreads();
    }
    float4 bv = *(const float4*)&bias[n0 + tx * 4];
#pragma unroll
    for (int i = 0; i < 4; i++) {
        float4 v;
        unpack2(acc[i][0], v.x, v.y);
        unpack2(acc[i][1], v.z, v.w);
        v.x += bv.x; v.y += bv.y; v.z += bv.z; v.w += bv.w;
        *(float4*)&g_xp[t * BH + (ty * 4 + i) * DH + n0 + tx * 4] = v;
    }
}

// ---------------------------------------------------------------------------
// Barrier (R9, proven): 4 row-group domains x 32 CTAs; one REDG arriver +
// one relaxed-spin poller per CTA, __syncthreads-coupled.
// ---------------------------------------------------------------------------
__device__ __forceinline__ unsigned int* rg_ctr(int rb, int t) {
    return &g_barG[(t * 4 + rb) * 32];
}

__device__ __forceinline__ void rg_barrier(int t, int rb, bool resetter) {
    __syncthreads();
    if (threadIdx.x == 0) {
        unsigned int* ctr = rg_ctr(rb, t);
        asm volatile("red.release.gpu.global.add.u32 [%0], 1;"
                     :: "l"(ctr) : "memory");
        unsigned int v;
        do {
            asm volatile("ld.relaxed.gpu.global.u32 %0, [%1];"
                         : "=r"(v) : "l"(ctr) : "memory");
        } while (v < DOM_ARRIVALS);
        asm volatile("ld.acquire.gpu.global.u32 %0, [%1];"
                     : "=r"(v) : "l"(ctr) : "memory");
        if (resetter && t > 0) {
            asm volatile("st.relaxed.gpu.global.u32 [%0], 0;"
                         :: "l"(rg_ctr(rb, t - 1)) : "memory");
        }
    }
    __syncthreads();
}

// ---------------------------------------------------------------------------
// Kernel B: persistent scan on TENSOR CORES (mma.sync m16n8k16 bf16,
// split-precision: h = hi+lo bf16, W = Whi+Wlo bf16, 3 products).
// 128 CTAs: (rb = bid>>5) rows [16rb,16rb+16), (cb = bid&31) cols
// [32cb,32cb+32). 8 warps split K: warp w owns k in [128w,128w+128).
// W fragments live in 128 regs/lane for the whole kernel.
// Per step: stage h(t-1) rows (hi+lo, 64KB) into SMEM once -> ldmatrix ->
// 96 HMMA/warp -> SMEM K-reduction over 8 warps -> +xp, tanh, split, store.
// ---------------------------------------------------------------------------
__device__ __forceinline__ void mma_bf16(float& d0, float& d1, float& d2, float& d3,
                                         uint32 a0, uint32 a1, uint32 a2, uint32 a3,
                                         uint32 b0, uint32 b1) {
    asm volatile(
        "mma.sync.aligned.m16n8k16.row.col.f32.bf16.bf16.f32 "
        "{%0,%1,%2,%3}, {%4,%5,%6,%7}, {%8,%9}, {%0,%1,%2,%3};"
        : "+f"(d0), "+f"(d1), "+f"(d2), "+f"(d3)
        : "r"(a0), "r"(a1), "r"(a2), "r"(a3), "r"(b0), "r"(b1));
}

__device__ __forceinline__ void ldsm_x4(uint32& r0, uint32& r1, uint32& r2, uint32& r3,
                                        uint32 saddr) {
    asm volatile("ldmatrix.sync.aligned.m8n8.x4.shared.b16 {%0,%1,%2,%3}, [%4];"
                 : "=r"(r0), "=r"(r1), "=r"(r2), "=r"(r3) : "r"(saddr));
}

__global__ void __launch_bounds__(256, 1) k_scan(const float* __restrict__ Wh) {
    extern __shared__ __align__(16) char smem_raw[];
    __nv_bfloat16* sA_hi = (__nv_bfloat16*)smem_raw;                  // [16][SA_STRIDE]
    __nv_bfloat16* sA_lo = sA_hi + 16 * SA_STRIDE;                    // [16][SA_STRIDE]
    float*         sRed  = (float*)(sA_lo + 16 * SA_STRIDE);          // [8][512]

    const int tid  = threadIdx.x;
    const int w    = tid >> 5;
    const int lane = tid & 31;
    const int rb   = blockIdx.x >> 5;          // 0..3 row group
    const int cb   = blockIdx.x & 31;          // 0..31 col block
    const int row0 = rb * 16;
    const bool resetter = (cb == 0);

    if (resetter && tid == 0) {
        *rg_ctr(rb, T_STEPS - 2) = 0;
    }

    // ---- preload W fragments (hi/lo) into registers -----------------------
    // B frag (n8k16, col layout): b0 = {W[k][n], W[k+1][n]}, b1 = {W[k+8][n], W[k+9][n]}
    // with n = cb*32 + nt*8 + (lane>>2), k = w*128 + kt*16 + 2*(lane&3).
    uint32 Bhi[4][8][2], Blo[4][8][2];
    {
        const int nn = cb * 32 + (lane >> 2);
#pragma unroll
        for (int nt = 0; nt < 4; nt++) {
            const int n = nn + nt * 8;
#pragma unroll
            for (int kt = 0; kt < 8; kt++) {
                const int kbase = w * 128 + kt * 16 + 2 * (lane & 3);
#pragma unroll
                for (int half = 0; half < 2; half++) {
                    const int k = kbase + half * 8;
                    float w0 = Wh[k * DH + n];
                    float w1 = Wh[(k + 1) * DH + n];
                    __nv_bfloat16 h0, l0, h1, l1;
                    split_bf16(w0, h0, l0);
                    split_bf16(w1, h1, l1);
                    Bhi[nt][kt][half] = pack_bf2(h0, h1);
                    Blo[nt][kt][half] = pack_bf2(l0, l1);
                }
            }
        }
    }

    // epilogue thread mapping: thread -> 2 adjacent outputs
    const int erow = tid >> 4;                 // 0..15 local row
    const int ecol = (tid & 15) * 2;           // 0..30 local col (even)
    const int grow = row0 + erow;
    const int gcol = cb * 32 + ecol;

    // ---- t = 0: h = tanh(xp) ---------------------------------------------
    {
        float2 xv = *(const float2*)&g_xp[grow * DH + gcol];
        float v0 = tanhf(xv.x), v1 = tanhf(xv.y);
        __nv_bfloat16 h0, l0, h1, l1;
        split_bf16(v0, h0, l0);
        split_bf16(v1, h1, l1);
        *(uint32*)&g_hs_hi[grow * DH + gcol] = pack_bf2(h0, h1);
        *(uint32*)&g_hs_lo[grow * DH + gcol] = pack_bf2(l0, l1);
    }
    rg_barrier(0, rb, resetter);

    // ldmatrix source address (byte, shared) for this lane, per (kt):
    // row = lane&15, k-offset = w*128 + kt*16 + (lane>>4)*8
    uint32 sa_hi_base = (uint32)__cvta_generic_to_shared(sA_hi);
    uint32 sa_lo_base = (uint32)__cvta_generic_to_shared(sA_lo);
    const uint32 lane_off = ((uint32)(lane & 15) * SA_STRIDE + (uint32)(w * 128) +
                            (uint32)((lane >> 4) * 8)) * 2u;

    for (int t = 1; t < T_STEPS; t++) {
        // prefetch xp (independent of h)
        float2 xv = *(const float2*)&g_xp[t * BH + grow * DH + gcol];

        // ---- stage h(t-1) rows [row0,row0+16) hi+lo into SMEM ------------
        {
            const uint4* srcH = (const uint4*)(g_hs_hi + (size_t)(t - 1) * BH + row0 * DH);
            const uint4* srcL = (const uint4*)(g_hs_lo + (size_t)(t - 1) * BH + row0 * DH);
#pragma unroll
            for (int i = 0; i < 8; i++) {
                int c   = tid + 256 * i;       // 0..2047 chunks of 8 bf16
                int row = c >> 7;
                int off = c & 127;
                *(uint4*)(sA_hi + row * SA_STRIDE + off * 8) = srcH[c];
                *(uint4*)(sA_lo + row * SA_STRIDE + off * 8) = srcL[c];
            }
        }
        __syncthreads();

        // ---- MMA: 8 k-tiles x 4 n-tiles x 3 products ---------------------
        float C[4][4];
#pragma unroll
        for (int nt = 0; nt < 4; nt++)
#pragma unroll
            for (int i = 0; i < 4; i++) C[nt][i] = 0.f;

#pragma unroll
        for (int kt = 0; kt < 8; kt++) {
            uint32 ah0, ah1, ah2, ah3, al0, al1, al2, al3;
            ldsm_x4(ah0, ah1, ah2, ah3, sa_hi_base + lane_off + (uint32)(kt * 32));
            ldsm_x4(al0, al1, al2, al3, sa_lo_base + lane_off + (uint32)(kt * 32));
#pragma unroll
            for (int nt = 0; nt < 4; nt++) {
                mma_bf16(C[nt][0], C[nt][1], C[nt][2], C[nt][3],
                         ah0, ah1, ah2, ah3, Bhi[nt][kt][0], Bhi[nt][kt][1]);
                mma_bf16(C[nt][0], C[nt][1], C[nt][2], C[nt][3],
                         ah0, ah1, ah2, ah3, Blo[nt][kt][0], Blo[nt][kt][1]);
                mma_bf16(C[nt][0], C[nt][1], C[nt][2], C[nt][3],
                         al0, al1, al2, al3, Bhi[nt][kt][0], Bhi[nt][kt][1]);
            }
        }

        // ---- write K-partials to SMEM ------------------------------------
        // C frag: c0,c1 -> (g, 2q), (g, 2q+1); c2,c3 -> (g+8, ...), g=lane>>2, q=lane&3
        {
            const int g = lane >> 2;
            const int q = lane & 3;
            float* base = sRed + w * 512;
#pragma unroll
            for (int nt = 0; nt < 4; nt++) {
                const int coln = nt * 8 + 2 * q;
                float2 lo2; lo2.x = C[nt][0]; lo2.y = C[nt][1];
                float2 hi2; hi2.x = C[nt][2]; hi2.y = C[nt][3];
                *(float2*)&base[g * 32 + coln]        = lo2;
                *(float2*)&base[(g + 8) * 32 + coln]  = hi2;
            }
        }
        __syncthreads();

        // ---- reduce 8 warp-partials, add xp, tanh, split, store ----------
        {
            const int o = erow * 32 + ecol;
            float2 s = {0.f, 0.f};
#pragma unroll
            for (int ww = 0; ww < 8; ww++) {
                float2 v = *(const float2*)&sRed[ww * 512 + o];
                s.x += v.x;
                s.y += v.y;
            }
            float v0 = tanhf(xv.x + s.x);
            float v1 = tanhf(xv.y + s.y);
            __nv_bfloat16 h0, l0, h1, l1;
            split_bf16(v0, h0, l0);
            split_bf16(v1, h1, l1);
            *(uint32*)&g_hs_hi[(size_t)t * BH + grow * DH + gcol] = pack_bf2(h0, h1);
            *(uint32*)&g_hs_lo[(size_t)t * BH + grow * DH + gcol] = pack_bf2(l0, l1);
        }

        if (t != T_STEPS - 1)
            rg_barrier(t, rb, resetter);
    }
}

// ---------------------------------------------------------------------------
// Kernel C: out[b][t][o] = sum_h hs[t][b][h] * W_out[h][o] + bias[o]
// (hs reconstructed as hi + lo)
// ---------------------------------------------------------------------------
__global__ void k_out(const float* __restrict__ Wo,
                      const float* __restrict__ bias,
                      float* __restrict__ out) {
    const int t  = blockIdx.x;
    const int n0 = blockIdx.y * 64;
    __shared__ __align__(16) float As[64][36];
    __shared__ __align__(16) float Bs[32][68];
    const int tid = threadIdx.x;
    const int ty = tid >> 4, tx = tid & 15;
    ull acc[4][2] = {};

    for (int k0 = 0; k0 < DH; k0 += 32) {
        for (int i = tid; i < 64 * 32; i += 256) {
            int m = i >> 5, kk = i & 31;
            size_t idx = (size_t)t * BH + m * DH + k0 + kk;
            As[m][kk] = __bfloat162float(g_hs_hi[idx]) + __bfloat162float(g_hs_lo[idx]);
        }
        for (int i = tid; i < 32 * 64; i += 256) {
            int kk = i >> 6, n = i & 63;
            Bs[kk][n] = Wo[(k0 + kk) * DOUT + n0 + n];
        }
        __syncthreads();
#pragma unroll
        for (int kk = 0; kk < 32; kk++) {
            ulonglong2 bb = *(const ulonglong2*)&Bs[kk][tx * 4];
#pragma unroll
            for (int i = 0; i < 4; i++) {
                ull pa = pack2(As[ty * 4 + i][kk]);
                fma2(acc[i][0], pa, bb.x);
                fma2(acc[i][1], pa, bb.y);
            }
        }
        __syncthreads();
    }
    float4 bv = *(const float4*)&bias[n0 + tx * 4];
#pragma unroll
    for (int i = 0; i < 4; i++) {
        float4 v;
        unpack2(acc[i][0], v.x, v.y);
        unpack2(acc[i][1], v.z, v.w);
        v.x += bv.x; v.y += bv.y; v.z += bv.z; v.w += bv.w;
        *(float4*)&out[((ty * 4 + i) * T_STEPS + t) * DOUT + n0 + tx * 4] = v;
    }
}

// ---------------------------------------------------------------------------
extern "C" void kernel_launch(void* const* d_in, const int* in_sizes, int n_in,
                              void* d_out, int out_size) {
    const float* x  = (const float*)d_in[0];  // inputs [B,T,DIN]
    const float* Wi = (const float*)d_in[1];  // input_kernel [DIN,DH]
    const float* Wh = (const float*)d_in[2];  // hidden_kernel [DH,DH]
    const float* bh = (const float*)d_in[3];  // hidden_bias [DH]
    const float* Wo = (const float*)d_in[4];  // output_kernel [DH,DOUT]
    const float* bo = (const float*)d_in[5];  // output_bias [DOUT]
    float* out = (float*)d_out;               // [B,T,DOUT]

    const int scan_smem = 2 * 16 * SA_STRIDE * 2 + 8 * 512 * 4;  // 82432 B
    cudaFuncSetAttribute(k_scan, cudaFuncAttributeMaxDynamicSharedMemorySize,
                         scan_smem);

    k_xproj<<<dim3(T_STEPS, DH / 64), 256>>>(x, Wi, bh);
    k_scan<<<SCAN_CTAS, 256, scan_smem>>>(Wh);
    k_out<<<dim3(T_STEPS, DOUT / 64), 256>>>(Wo, bo, out);
}

// round 11
// speedup vs baseline: 5.7360x; 1.3999x over previous
#include <cuda_runtime.h>
#include <cuda_bf16.h>

#define T_STEPS 512
#define BATCH   64
#define DIN     256
#define DH      1024
#define DOUT    256
#define BH      (BATCH * DH)      // 65536
#define SCAN_CTAS 128
#define DOM_ARRIVALS 32           // 32 CTAs per row-group domain
#define SA_STRIDE 1032            // scan: padded bf16 row stride
#define AS 264                    // GEMM: padded bf16 row stride (528B = 16*33)

typedef unsigned long long ull;
typedef unsigned int uint32;

// Scratch (device globals: allocation-free per harness rules)
__device__ float g_xp[T_STEPS * BH];                 // [T][B][H] input projection
__device__ __nv_bfloat16 g_hs_hi[T_STEPS * BH];      // h high bf16
__device__ __nv_bfloat16 g_hs_lo[T_STEPS * BH];      // h residual bf16
__device__ unsigned int g_barG[T_STEPS * 4 * 32];    // (step, rowgroup) counters
__device__ uint4 g_WiF[128 * 16 * 32];               // W_in  B-frags [nblk][kt][lane]
__device__ uint4 g_WoF[32 * 64 * 32];                // W_out B-frags [nblk][kt][lane]

// ---- bf16 split helpers ---------------------------------------------------
__device__ __forceinline__ void split_bf16(float v, __nv_bfloat16& hi, __nv_bfloat16& lo) {
    hi = __float2bfloat16_rn(v);
    lo = __float2bfloat16_rn(v - __bfloat162float(hi));
}
__device__ __forceinline__ uint32 pack_bf2(__nv_bfloat16 a, __nv_bfloat16 b) {
    __nv_bfloat162 p;
    p.x = a; p.y = b;
    return *(uint32*)&p;
}

// ---- mma / ldmatrix helpers (validated in R10 scan) -----------------------
__device__ __forceinline__ void mma_bf16(float& d0, float& d1, float& d2, float& d3,
                                         uint32 a0, uint32 a1, uint32 a2, uint32 a3,
                                         uint32 b0, uint32 b1) {
    asm volatile(
        "mma.sync.aligned.m16n8k16.row.col.f32.bf16.bf16.f32 "
        "{%0,%1,%2,%3}, {%4,%5,%6,%7}, {%8,%9}, {%0,%1,%2,%3};"
        : "+f"(d0), "+f"(d1), "+f"(d2), "+f"(d3)
        : "r"(a0), "r"(a1), "r"(a2), "r"(a3), "r"(b0), "r"(b1));
}
__device__ __forceinline__ void ldsm_x4(uint32& r0, uint32& r1, uint32& r2, uint32& r3,
                                        uint32 saddr) {
    asm volatile("ldmatrix.sync.aligned.m8n8.x4.shared.b16 {%0,%1,%2,%3}, [%4];"
                 : "=r"(r0), "=r"(r1), "=r"(r2), "=r"(r3) : "r"(saddr));
}

// ---------------------------------------------------------------------------
// Prep: build split-bf16 B-fragment arrays for W_in and W_out.
// Frag layout per (nblk, kt, lane): b0={W[k][n],W[k+1][n]}, b1={W[k+8][n],W[k+9][n]}
// with n = nblk*8 + (lane>>2), k = kt*16 + 2*(lane&3)  (validated in scan).
// uint4 = (b0_hi, b1_hi, b0_lo, b1_lo).
// ---------------------------------------------------------------------------
__device__ __forceinline__ uint4 make_frag(const float* __restrict__ W, int ldn,
                                           int n, int k) {
    float w00 = W[k * ldn + n],       w01 = W[(k + 1) * ldn + n];
    float w10 = W[(k + 8) * ldn + n], w11 = W[(k + 9) * ldn + n];
    __nv_bfloat16 h00, l00, h01, l01, h10, l10, h11, l11;
    split_bf16(w00, h00, l00); split_bf16(w01, h01, l01);
    split_bf16(w10, h10, l10); split_bf16(w11, h11, l11);
    uint4 v;
    v.x = pack_bf2(h00, h01);
    v.y = pack_bf2(h10, h11);
    v.z = pack_bf2(l00, l01);
    v.w = pack_bf2(l10, l11);
    return v;
}

__global__ void k_prep(const float* __restrict__ Wi, const float* __restrict__ Wo) {
    int idx = blockIdx.x * 256 + threadIdx.x;
    if (idx < 128 * 16 * 32) {            // W_in frags: nblk<128, kt<16
        int lane = idx & 31;
        int kt   = (idx >> 5) & 15;
        int nblk = idx >> 9;
        g_WiF[idx] = make_frag(Wi, DH, nblk * 8 + (lane >> 2), kt * 16 + 2 * (lane & 3));
    } else {                               // W_out frags: nblk<32, kt<64
        int j = idx - 128 * 16 * 32;
        int lane = j & 31;
        int kt   = (j >> 5) & 63;
        int nblk = j >> 11;
        g_WoF[j] = make_frag(Wo, DOUT, nblk * 8 + (lane >> 2), kt * 16 + 2 * (lane & 3));
    }
}

// ---------------------------------------------------------------------------
// Kernel A (tensor): x_proj = x @ W_in + bias.  CTA: t fixed, m64(b) x n128,
// K=256 single chunk. 8 warps: mt = w&3 (16 rows), nh = w>>2 (n64 half).
// ---------------------------------------------------------------------------
__global__ void __launch_bounds__(256, 1) k_xproj_mma(const float* __restrict__ x,
                                                      const float* __restrict__ bias) {
    extern __shared__ __align__(16) char smem_raw[];
    __nv_bfloat16* sAhi = (__nv_bfloat16*)smem_raw;   // [64][AS]
    __nv_bfloat16* sAlo = sAhi + 64 * AS;

    const int tid = threadIdx.x, w = tid >> 5, lane = tid & 31;
    const int t = blockIdx.x, n0 = blockIdx.y * 128;
    const int mt = w & 3, nh = w >> 2;

    // fill A: 64 rows x 256 fp32 -> split hi/lo bf16
#pragma unroll
    for (int i = 0; i < 16; i++) {
        int c = tid + 256 * i;
        int row = c >> 6, off = c & 63;
        float4 v = ((const float4*)(x + ((size_t)row * T_STEPS + t) * DIN))[off];
        __nv_bfloat16 h0, l0, h1, l1, h2, l2, h3, l3;
        split_bf16(v.x, h0, l0); split_bf16(v.y, h1, l1);
        split_bf16(v.z, h2, l2); split_bf16(v.w, h3, l3);
        uint2 ph, pl;
        ph.x = pack_bf2(h0, h1); ph.y = pack_bf2(h2, h3);
        pl.x = pack_bf2(l0, l1); pl.y = pack_bf2(l2, l3);
        *(uint2*)&sAhi[row * AS + off * 4] = ph;
        *(uint2*)&sAlo[row * AS + off * 4] = pl;
    }
    __syncthreads();

    float C[8][4] = {};
    uint32 abase_hi = (uint32)__cvta_generic_to_shared(sAhi);
    uint32 abase_lo = (uint32)__cvta_generic_to_shared(sAlo);
    const uint32 lane_off = ((uint32)((mt * 16 + (lane & 15)) * AS) +
                            (uint32)((lane >> 4) * 8)) * 2u;

#pragma unroll
    for (int kt = 0; kt < 16; kt++) {
        uint32 ah0, ah1, ah2, ah3, al0, al1, al2, al3;
        ldsm_x4(ah0, ah1, ah2, ah3, abase_hi + lane_off + (uint32)(kt * 32));
        ldsm_x4(al0, al1, al2, al3, abase_lo + lane_off + (uint32)(kt * 32));
#pragma unroll
        for (int nt = 0; nt < 8; nt++) {
            int nblk = (n0 >> 3) + nh * 8 + nt;
            uint4 bf = g_WiF[(nblk * 16 + kt) * 32 + lane];
            mma_bf16(C[nt][0], C[nt][1], C[nt][2], C[nt][3],
                     ah0, ah1, ah2, ah3, bf.x, bf.y);
            mma_bf16(C[nt][0], C[nt][1], C[nt][2], C[nt][3],
                     ah0, ah1, ah2, ah3, bf.z, bf.w);
            mma_bf16(C[nt][0], C[nt][1], C[nt][2], C[nt][3],
                     al0, al1, al2, al3, bf.x, bf.y);
        }
    }

    const int g = lane >> 2, q = lane & 3;
#pragma unroll
    for (int nt = 0; nt < 8; nt++) {
        int n = n0 + nh * 64 + nt * 8 + 2 * q;
        float2 bv = *(const float2*)&bias[n];
        int m0 = mt * 16 + g;
        float2 v0; v0.x = C[nt][0] + bv.x; v0.y = C[nt][1] + bv.y;
        *(float2*)&g_xp[(size_t)t * BH + m0 * DH + n] = v0;
        float2 v1; v1.x = C[nt][2] + bv.x; v1.y = C[nt][3] + bv.y;
        *(float2*)&g_xp[(size_t)t * BH + (m0 + 8) * DH + n] = v1;
    }
}

// ---------------------------------------------------------------------------
// Barrier (R9, proven)
// ---------------------------------------------------------------------------
__device__ __forceinline__ unsigned int* rg_ctr(int rb, int t) {
    return &g_barG[(t * 4 + rb) * 32];
}

__device__ __forceinline__ void rg_barrier(int t, int rb, bool resetter) {
    __syncthreads();
    if (threadIdx.x == 0) {
        unsigned int* ctr = rg_ctr(rb, t);
        asm volatile("red.release.gpu.global.add.u32 [%0], 1;"
                     :: "l"(ctr) : "memory");
        unsigned int v;
        do {
            asm volatile("ld.relaxed.gpu.global.u32 %0, [%1];"
                         : "=r"(v) : "l"(ctr) : "memory");
        } while (v < DOM_ARRIVALS);
        asm volatile("ld.acquire.gpu.global.u32 %0, [%1];"
                     : "=r"(v) : "l"(ctr) : "memory");
        if (resetter && t > 0) {
            asm volatile("st.relaxed.gpu.global.u32 [%0], 0;"
                         :: "l"(rg_ctr(rb, t - 1)) : "memory");
        }
    }
    __syncthreads();
}

// ---------------------------------------------------------------------------
// Kernel B: persistent tensor-core scan (R10, unchanged — proven 3.8us/step)
// ---------------------------------------------------------------------------
__global__ void __launch_bounds__(256, 1) k_scan(const float* __restrict__ Wh) {
    extern __shared__ __align__(16) char smem_raw[];
    __nv_bfloat16* sA_hi = (__nv_bfloat16*)smem_raw;                  // [16][SA_STRIDE]
    __nv_bfloat16* sA_lo = sA_hi + 16 * SA_STRIDE;                    // [16][SA_STRIDE]
    float*         sRed  = (float*)(sA_lo + 16 * SA_STRIDE);          // [8][512]

    const int tid  = threadIdx.x;
    const int w    = tid >> 5;
    const int lane = tid & 31;
    const int rb   = blockIdx.x >> 5;
    const int cb   = blockIdx.x & 31;
    const int row0 = rb * 16;
    const bool resetter = (cb == 0);

    if (resetter && tid == 0) {
        *rg_ctr(rb, T_STEPS - 2) = 0;
    }

    uint32 Bhi[4][8][2], Blo[4][8][2];
    {
        const int nn = cb * 32 + (lane >> 2);
#pragma unroll
        for (int nt = 0; nt < 4; nt++) {
            const int n = nn + nt * 8;
#pragma unroll
            for (int kt = 0; kt < 8; kt++) {
                const int kbase = w * 128 + kt * 16 + 2 * (lane & 3);
#pragma unroll
                for (int half = 0; half < 2; half++) {
                    const int k = kbase + half * 8;
                    float w0 = Wh[k * DH + n];
                    float w1 = Wh[(k + 1) * DH + n];
                    __nv_bfloat16 h0, l0, h1, l1;
                    split_bf16(w0, h0, l0);
                    split_bf16(w1, h1, l1);
                    Bhi[nt][kt][half] = pack_bf2(h0, h1);
                    Blo[nt][kt][half] = pack_bf2(l0, l1);
                }
            }
        }
    }

    const int erow = tid >> 4;
    const int ecol = (tid & 15) * 2;
    const int grow = row0 + erow;
    const int gcol = cb * 32 + ecol;

    {
        float2 xv = *(const float2*)&g_xp[grow * DH + gcol];
        float v0 = tanhf(xv.x), v1 = tanhf(xv.y);
        __nv_bfloat16 h0, l0, h1, l1;
        split_bf16(v0, h0, l0);
        split_bf16(v1, h1, l1);
        *(uint32*)&g_hs_hi[grow * DH + gcol] = pack_bf2(h0, h1);
        *(uint32*)&g_hs_lo[grow * DH + gcol] = pack_bf2(l0, l1);
    }
    rg_barrier(0, rb, resetter);

    uint32 sa_hi_base = (uint32)__cvta_generic_to_shared(sA_hi);
    uint32 sa_lo_base = (uint32)__cvta_generic_to_shared(sA_lo);
    const uint32 lane_off = ((uint32)(lane & 15) * SA_STRIDE + (uint32)(w * 128) +
                            (uint32)((lane >> 4) * 8)) * 2u;

    for (int t = 1; t < T_STEPS; t++) {
        float2 xv = *(const float2*)&g_xp[t * BH + grow * DH + gcol];

        {
            const uint4* srcH = (const uint4*)(g_hs_hi + (size_t)(t - 1) * BH + row0 * DH);
            const uint4* srcL = (const uint4*)(g_hs_lo + (size_t)(t - 1) * BH + row0 * DH);
#pragma unroll
            for (int i = 0; i < 8; i++) {
                int c   = tid + 256 * i;
                int row = c >> 7;
                int off = c & 127;
                *(uint4*)(sA_hi + row * SA_STRIDE + off * 8) = srcH[c];
                *(uint4*)(sA_lo + row * SA_STRIDE + off * 8) = srcL[c];
            }
        }
        __syncthreads();

        float C[4][4];
#pragma unroll
        for (int nt = 0; nt < 4; nt++)
#pragma unroll
            for (int i = 0; i < 4; i++) C[nt][i] = 0.f;

#pragma unroll
        for (int kt = 0; kt < 8; kt++) {
            uint32 ah0, ah1, ah2, ah3, al0, al1, al2, al3;
            ldsm_x4(ah0, ah1, ah2, ah3, sa_hi_base + lane_off + (uint32)(kt * 32));
            ldsm_x4(al0, al1, al2, al3, sa_lo_base + lane_off + (uint32)(kt * 32));
#pragma unroll
            for (int nt = 0; nt < 4; nt++) {
                mma_bf16(C[nt][0], C[nt][1], C[nt][2], C[nt][3],
                         ah0, ah1, ah2, ah3, Bhi[nt][kt][0], Bhi[nt][kt][1]);
                mma_bf16(C[nt][0], C[nt][1], C[nt][2], C[nt][3],
                         ah0, ah1, ah2, ah3, Blo[nt][kt][0], Blo[nt][kt][1]);
                mma_bf16(C[nt][0], C[nt][1], C[nt][2], C[nt][3],
                         al0, al1, al2, al3, Bhi[nt][kt][0], Bhi[nt][kt][1]);
            }
        }

        {
            const int g = lane >> 2;
            const int q = lane & 3;
            float* base = sRed + w * 512;
#pragma unroll
            for (int nt = 0; nt < 4; nt++) {
                const int coln = nt * 8 + 2 * q;
                float2 lo2; lo2.x = C[nt][0]; lo2.y = C[nt][1];
                float2 hi2; hi2.x = C[nt][2]; hi2.y = C[nt][3];
                *(float2*)&base[g * 32 + coln]        = lo2;
                *(float2*)&base[(g + 8) * 32 + coln]  = hi2;
            }
        }
        __syncthreads();

        {
            const int o = erow * 32 + ecol;
            float2 s = {0.f, 0.f};
#pragma unroll
            for (int ww = 0; ww < 8; ww++) {
                float2 v = *(const float2*)&sRed[ww * 512 + o];
                s.x += v.x;
                s.y += v.y;
            }
            float v0 = tanhf(xv.x + s.x);
            float v1 = tanhf(xv.y + s.y);
            __nv_bfloat16 h0, l0, h1, l1;
            split_bf16(v0, h0, l0);
            split_bf16(v1, h1, l1);
            *(uint32*)&g_hs_hi[(size_t)t * BH + grow * DH + gcol] = pack_bf2(h0, h1);
            *(uint32*)&g_hs_lo[(size_t)t * BH + grow * DH + gcol] = pack_bf2(l0, l1);
        }

        if (t != T_STEPS - 1)
            rg_barrier(t, rb, resetter);
    }
}

// ---------------------------------------------------------------------------
// Kernel C (tensor): out = hs @ W_out + bias. CTA: t fixed, m64(b) x n128,
// K=1024 in 4 chunks of 256. A is already split bf16 in g_hs_hi/lo.
// ---------------------------------------------------------------------------
__global__ void __launch_bounds__(256, 1) k_out_mma(const float* __restrict__ bias,
                                                    float* __restrict__ out) {
    extern __shared__ __align__(16) char smem_raw[];
    __nv_bfloat16* sAhi = (__nv_bfloat16*)smem_raw;   // [64][AS]
    __nv_bfloat16* sAlo = sAhi + 64 * AS;

    const int tid = threadIdx.x, w = tid >> 5, lane = tid & 31;
    const int t = blockIdx.x, n0 = blockIdx.y * 128;
    const int mt = w & 3, nh = w >> 2;

    float C[8][4] = {};
    uint32 abase_hi = (uint32)__cvta_generic_to_shared(sAhi);
    uint32 abase_lo = (uint32)__cvta_generic_to_shared(sAlo);
    const uint32 lane_off = ((uint32)((mt * 16 + (lane & 15)) * AS) +
                            (uint32)((lane >> 4) * 8)) * 2u;

    for (int kc = 0; kc < 4; kc++) {
        // stage A chunk: 64 rows x 256 bf16, hi + lo
#pragma unroll
        for (int i = 0; i < 8; i++) {
            int c = tid + 256 * i;
            int row = c >> 5, off = c & 31;
            size_t gidx = (size_t)t * BH + row * DH + kc * 256 + off * 8;
            *(uint4*)&sAhi[row * AS + off * 8] = *(const uint4*)&g_hs_hi[gidx];
            *(uint4*)&sAlo[row * AS + off * 8] = *(const uint4*)&g_hs_lo[gidx];
        }
        __syncthreads();

#pragma unroll
        for (int kt = 0; kt < 16; kt++) {
            int ktg = kc * 16 + kt;
            uint32 ah0, ah1, ah2, ah3, al0, al1, al2, al3;
            ldsm_x4(ah0, ah1, ah2, ah3, abase_hi + lane_off + (uint32)(kt * 32));
            ldsm_x4(al0, al1, al2, al3, abase_lo + lane_off + (uint32)(kt * 32));
#pragma unroll
            for (int nt = 0; nt < 8; nt++) {
                int nblk = (n0 >> 3) + nh * 8 + nt;
                uint4 bf = g_WoF[(nblk * 64 + ktg) * 32 + lane];
                mma_bf16(C[nt][0], C[nt][1], C[nt][2], C[nt][3],
                         ah0, ah1, ah2, ah3, bf.x, bf.y);
                mma_bf16(C[nt][0], C[nt][1], C[nt][2], C[nt][3],
                         ah0, ah1, ah2, ah3, bf.z, bf.w);
                mma_bf16(C[nt][0], C[nt][1], C[nt][2], C[nt][3],
                         al0, al1, al2, al3, bf.x, bf.y);
            }
        }
        __syncthreads();
    }

    const int g = lane >> 2, q = lane & 3;
#pragma unroll
    for (int nt = 0; nt < 8; nt++) {
        int n = n0 + nh * 64 + nt * 8 + 2 * q;
        float2 bv = *(const float2*)&bias[n];
        int m0 = mt * 16 + g;
        float2 v0; v0.x = C[nt][0] + bv.x; v0.y = C[nt][1] + bv.y;
        *(float2*)&out[((size_t)m0 * T_STEPS + t) * DOUT + n] = v0;
        float2 v1; v1.x = C[nt][2] + bv.x; v1.y = C[nt][3] + bv.y;
        *(float2*)&out[((size_t)(m0 + 8) * T_STEPS + t) * DOUT + n] = v1;
    }
}

// ---------------------------------------------------------------------------
extern "C" void kernel_launch(void* const* d_in, const int* in_sizes, int n_in,
                              void* d_out, int out_size) {
    const float* x  = (const float*)d_in[0];  // inputs [B,T,DIN]
    const float* Wi = (const float*)d_in[1];  // input_kernel [DIN,DH]
    const float* Wh = (const float*)d_in[2];  // hidden_kernel [DH,DH]
    const float* bh = (const float*)d_in[3];  // hidden_bias [DH]
    const float* Wo = (const float*)d_in[4];  // output_kernel [DH,DOUT]
    const float* bo = (const float*)d_in[5];  // output_bias [DOUT]
    float* out = (float*)d_out;               // [B,T,DOUT]

    const int scan_smem = 2 * 16 * SA_STRIDE * 2 + 8 * 512 * 4;  // 82432 B
    cudaFuncSetAttribute(k_scan, cudaFuncAttributeMaxDynamicSharedMemorySize,
                         scan_smem);
    const int gemm_smem = 2 * 64 * AS * 2;                       // 67584 B
    cudaFuncSetAttribute(k_xproj_mma, cudaFuncAttributeMaxDynamicSharedMemorySize,
                         gemm_smem);
    cudaFuncSetAttribute(k_out_mma, cudaFuncAttributeMaxDynamicSharedMemorySize,
                         gemm_smem);

    k_prep<<<(128 * 16 * 32 + 32 * 64 * 32) / 256, 256>>>(Wi, Wo);
    k_xproj_mma<<<dim3(T_STEPS, 8), 256, gemm_smem>>>(x, bh);
    k_scan<<<SCAN_CTAS, 256, scan_smem>>>(Wh);
    k_out_mma<<<dim3(T_STEPS, 2), 256, gemm_smem>>>(bo, out);
}